// round 15
// baseline (speedup 1.0000x reference)
#include <cuda_runtime.h>
#include <cuda_fp16.h>
#include <cstdint>

#define NFIELDS 32
#define EMBED   64
#define NPAIRS  496
#define BATCH   2048
#define EMB_ROW 2048                // halves per batch row (32*64)
#define KER_ROW 31744               // halves per i row (496*64)
#define EMB_N   (BATCH * NFIELDS * EMBED)   // 4194304
#define KER_N   (EMBED * NPAIRS * EMBED)    // 2031616
#define EMB_SLOTS (EMB_N / 4)               // float4 slots (1048576)
#define KER_SLOTS (KER_N / 4)               // 507904

#define BM      256                 // batches per block
#define PCHUNK  4                   // pairs per block (all share one r)
#define NCHUNKS 136                 // sum over r of ceil((31-r)/4)
#define NTHREADS 256

#define ASTR 72                     // A row stride (halves): conflict-free
#define BSTR 72                     // B row stride (halves)
#define A_HALVES (BM * ASTR)        // 18432
#define B_HALVES (EMBED * BSTR)     // 4608

// fp16 copies of the inputs (filled by conversion pre-pass)
__device__ __half g_emb_h[EMB_N];
__device__ __half g_ker_h[KER_N];

// 4 float4 slots per thread (MLP=4): 1024 emb blocks + 496 ker blocks
#define EMB_CONV_BLOCKS (EMB_SLOTS / 4 / 256)   // 1024
#define KER_CONV_BLOCKS (KER_SLOTS / 4 / 256)   // 496

__global__ void conv_kernel(const float* __restrict__ emb,
                            const float* __restrict__ ker) {
    const float4* src;
    uint2* dst;
    int base;
    if (blockIdx.x < EMB_CONV_BLOCKS) {
        src = (const float4*)emb; dst = (uint2*)g_emb_h;
        base = (blockIdx.x * 256 + threadIdx.x) * 4;
    } else {
        src = (const float4*)ker; dst = (uint2*)g_ker_h;
        base = ((blockIdx.x - EMB_CONV_BLOCKS) * 256 + threadIdx.x) * 4;
    }
    float4 v[4];
    #pragma unroll
    for (int u = 0; u < 4; ++u) v[u] = src[base + u];   // 4 LDGs in flight
    #pragma unroll
    for (int u = 0; u < 4; ++u) {
        __half2 h0 = __floats2half2_rn(v[u].x, v[u].y);
        __half2 h1 = __floats2half2_rn(v[u].z, v[u].w);
        uint2 w;
        w.x = *reinterpret_cast<uint32_t*>(&h0);
        w.y = *reinterpret_cast<uint32_t*>(&h1);
        dst[base + u] = w;
    }
}

__device__ __forceinline__ void mma_f16(float* d, uint32_t a0, uint32_t a1,
                                        uint32_t a2, uint32_t a3,
                                        uint32_t b0, uint32_t b1) {
    asm("mma.sync.aligned.m16n8k16.row.col.f32.f16.f16.f32 "
        "{%0,%1,%2,%3}, {%4,%5,%6,%7}, {%8,%9}, {%0,%1,%2,%3};"
        : "+f"(d[0]), "+f"(d[1]), "+f"(d[2]), "+f"(d[3])
        : "r"(a0), "r"(a1), "r"(a2), "r"(a3), "r"(b0), "r"(b1));
}

// N-dim permutation (dense q loads): GEMM col n = 16T+8h+2m+u holds
// physical i = phi(n) = 16m+4T+2h+u; rho = phi^{-1}.
__device__ __forceinline__ int rho_row(int i) {
    return (((i >> 2) & 3) << 4) | (((i >> 1) & 1) << 3) | (((i >> 4) & 3) << 1) | (i & 1);
}

__global__ void __launch_bounds__(NTHREADS, 2)
opn_mma_kernel(float* __restrict__ out)
{
    // smem (bytes): sA 36864 | sB 4 x 9216 | sOut 4096 -> 77824 B
    extern __shared__ __align__(16) __half dynsmem[];
    __half* sA   = dynsmem;
    __half* sB   = dynsmem + A_HALVES;
    float*  sOut = (float*)(sB + PCHUNK * B_HALVES);

    const int t    = threadIdx.x;
    const int ws   = t >> 5;    // warp strip: rows [ws*32, ws*32+32)
    const int lane = t & 31;
    const int m    = lane & 3;
    const int batch_base = blockIdx.x * BM;

    // ---- decode chunk id -> (r, first pair p0, #pairs np, first col c0) ----
    int cid = blockIdx.y, r = 0, pbase = 0;
    while (true) {
        int cnt = 31 - r;
        int nch = (cnt + PCHUNK - 1) >> 2;
        if (cid < nch) break;
        cid -= nch; pbase += cnt; ++r;
    }
    const int p0 = pbase + cid * PCHUNK;
    const int np = min(PCHUNK, (31 - r) - cid * PCHUNK);
    const int c0 = r + 1 + cid * PCHUNK;

    // ---- stage A: sA[b*ASTR + j] = emb_h[batch_base+b, r, j] ----
    {
        const __half* Pb = g_emb_h + (size_t)batch_base * EMB_ROW + r * EMBED;
        #pragma unroll
        for (int it = 0; it < 8; ++it) {
            int idx = it * NTHREADS + t;   // 0..2047 uint4 slots
            int b   = idx >> 3;            // 0..255
            int j8  = idx & 7;
            *(uint4*)(sA + b * ASTR + j8 * 8) =
                *(const uint4*)(Pb + (size_t)b * EMB_ROW + j8 * 8);
        }
    }
    // ---- stage all pairs' B tiles (one shot) ----
    {
        #pragma unroll
        for (int it = 0; it < 8; ++it) {
            int idx  = it * NTHREADS + t;  // 0..2047
            int pair = idx >> 9;           // 0..3
            int slot = idx & 511;
            if (pair < np) {
                int i  = slot >> 3;        // physical K row 0..63
                int j8 = slot & 7;
                *(uint4*)(sB + pair * B_HALVES + rho_row(i) * BSTR + j8 * 8) =
                    *(const uint4*)(g_ker_h + (size_t)(p0 + pair) * EMBED
                                    + (size_t)i * KER_ROW + j8 * 8);
            }
        }
    }
    __syncthreads();   // the ONLY barrier before the output sweep

    // ---- hoist A fragments into registers (shared across all pairs) ----
    const __half* Ap = sA + (ws * 32 + (lane >> 2)) * ASTR + 2 * m;
    uint32_t a[4][2][4];
    #pragma unroll
    for (int kt = 0; kt < 4; ++kt)
        #pragma unroll
        for (int mm = 0; mm < 2; ++mm) {
            const __half* Am = Ap + mm * 16 * ASTR + kt * 16;
            a[kt][mm][0] = *(const uint32_t*)(Am);
            a[kt][mm][1] = *(const uint32_t*)(Am + 8 * ASTR);
            a[kt][mm][2] = *(const uint32_t*)(Am + 8);
            a[kt][mm][3] = *(const uint32_t*)(Am + 8 * ASTR + 8);
        }

    const int bOff = (lane >> 2) * BSTR + 2 * m;

    // ---- barrier-free pair loop: all warps sweep pairs 0..np-1 ----
    #pragma unroll 1
    for (int j = 0; j < np; ++j) {
        const __half* Bp = sB + j * B_HALVES + bOff;

        float acc[2][8][4];
        #pragma unroll
        for (int mm = 0; mm < 2; ++mm)
            #pragma unroll
            for (int nt = 0; nt < 8; ++nt)
                #pragma unroll
                for (int u = 0; u < 4; ++u)
                    acc[mm][nt][u] = 0.f;

        #pragma unroll
        for (int kt = 0; kt < 4; ++kt) {
            #pragma unroll
            for (int nt = 0; nt < 8; ++nt) {
                const __half* Bn = Bp + nt * 8 * BSTR + kt * 16;
                uint32_t b0 = *(const uint32_t*)(Bn);
                uint32_t b1 = *(const uint32_t*)(Bn + 8);
                mma_f16(acc[0][nt], a[kt][0][0], a[kt][0][1], a[kt][0][2], a[kt][0][3], b0, b1);
                mma_f16(acc[1][nt], a[kt][1][0], a[kt][1][1], a[kt][1][2], a[kt][1][3], b0, b1);
            }
        }

        // ---- epilogue: dense q loads (lane m covers phys cols [16m,16m+16)) ----
        const int c = c0 + j;
        #pragma unroll
        for (int mm = 0; mm < 2; ++mm) {
            const int row0 = ws * 32 + mm * 16 + (lane >> 2);
            const __half* q0 = g_emb_h + (size_t)(batch_base + row0) * EMB_ROW
                             + c * EMBED + m * 16;
            const __half* q1 = q0 + 8 * EMB_ROW;

            uint4 lo0 = *(const uint4*)(q0);
            uint4 hi0 = *(const uint4*)(q0 + 8);
            uint4 lo1 = *(const uint4*)(q1);
            uint4 hi1 = *(const uint4*)(q1 + 8);

            float s0 = 0.f, s1 = 0.f;
            const uint32_t* w0[2] = { &lo0.x, &hi0.x };
            const uint32_t* w1[2] = { &lo1.x, &hi1.x };
            #pragma unroll
            for (int inst = 0; inst < 2; ++inst)
                #pragma unroll
                for (int p = 0; p < 4; ++p) {
                    float2 f0 = __half22float2(*reinterpret_cast<const __half2*>(&w0[inst][p]));
                    float2 f1 = __half22float2(*reinterpret_cast<const __half2*>(&w1[inst][p]));
                    const int nt = inst * 4 + p;
                    s0 += f0.x * acc[mm][nt][0] + f0.y * acc[mm][nt][1];
                    s1 += f1.x * acc[mm][nt][2] + f1.y * acc[mm][nt][3];
                }
            s0 += __shfl_xor_sync(0xffffffffu, s0, 1);
            s0 += __shfl_xor_sync(0xffffffffu, s0, 2);
            s1 += __shfl_xor_sync(0xffffffffu, s1, 1);
            s1 += __shfl_xor_sync(0xffffffffu, s1, 2);

            if (m == 0) {
                sOut[row0 * PCHUNK + j]       = s0;
                sOut[(row0 + 8) * PCHUNK + j] = s1;
            }
        }
    }
    __syncthreads();

    // ---- coalesced output sweep ----
    #pragma unroll
    for (int u = 0; u < 4; ++u) {
        int idx = t * 4 + u;               // 0..1023
        int b = idx >> 2;                  // 0..255
        int jj = idx & 3;
        if (jj < np)
            out[(size_t)(batch_base + b) * NPAIRS + p0 + jj] = sOut[idx];
    }
}

#define SMEM_TOTAL (A_HALVES * 2 + PCHUNK * B_HALVES * 2 + BM * PCHUNK * 4)  // 77824 B

extern "C" void kernel_launch(void* const* d_in, const int* in_sizes, int n_in,
                              void* d_out, int out_size) {
    const float* emb = (const float*)d_in[0];   // (2048, 32, 64) f32
    const float* ker = (const float*)d_in[1];   // (64, 496, 64) f32
    float* out = (float*)d_out;                 // (2048, 1, 496) f32
    (void)in_sizes; (void)n_in; (void)out_size;

    static bool attr_set = false;
    if (!attr_set) {
        cudaFuncSetAttribute(opn_mma_kernel,
                             cudaFuncAttributeMaxDynamicSharedMemorySize, SMEM_TOTAL);
        attr_set = true;
    }
    conv_kernel<<<EMB_CONV_BLOCKS + KER_CONV_BLOCKS, 256>>>(emb, ker);
    dim3 grid(BATCH / BM, NCHUNKS);
    opn_mma_kernel<<<grid, NTHREADS, SMEM_TOTAL>>>(out);
}

// round 16
// speedup vs baseline: 1.1405x; 1.1405x over previous
#include <cuda_runtime.h>
#include <cuda_fp16.h>
#include <cstdint>

#define NFIELDS 32
#define EMBED   64
#define NPAIRS  496
#define BATCH   2048
#define EMB_ROW 2048                // halves per batch row (32*64)
#define KER_ROW 31744               // halves per i row (496*64)
#define EMB_N   (BATCH * NFIELDS * EMBED)   // 4194304
#define KER_N   (EMBED * NPAIRS * EMBED)    // 2031616
#define EMB_SLOTS (EMB_N / 4)               // float4 slots (1048576)
#define KER_SLOTS (KER_N / 4)               // 507904

#define BM      256                 // batches per block
#define PCHUNK  4                   // pairs per block (all share one r)
#define NCHUNKS 136                 // sum over r of ceil((31-r)/4)
#define NTHREADS 256

#define ASTR 72                     // A row stride (halves): conflict-free
#define BSTR 72                     // B row stride (halves)
#define A_HALVES (BM * ASTR)        // 18432
#define B_HALVES (EMBED * BSTR)     // 4608

// fp16 copies of the inputs (filled by conversion pre-pass)
__device__ __half g_emb_h[EMB_N];
__device__ __half g_ker_h[KER_N];

// 4 float4 slots per thread, INTERLEAVED block-wide (coalesced + MLP=4)
#define EMB_CONV_BLOCKS (EMB_SLOTS / 4 / 256)   // 1024
#define KER_CONV_BLOCKS (KER_SLOTS / 4 / 256)   // 496

__global__ void conv_kernel(const float* __restrict__ emb,
                            const float* __restrict__ ker) {
    const float4* src;
    uint2* dst;
    int blk_base;
    if (blockIdx.x < EMB_CONV_BLOCKS) {
        src = (const float4*)emb; dst = (uint2*)g_emb_h;
        blk_base = blockIdx.x * 1024;
    } else {
        src = (const float4*)ker; dst = (uint2*)g_ker_h;
        blk_base = (blockIdx.x - EMB_CONV_BLOCKS) * 1024;
    }
    const int t = threadIdx.x;
    float4 v[4];
    #pragma unroll
    for (int u = 0; u < 4; ++u) v[u] = src[blk_base + u * 256 + t];  // coalesced, MLP=4
    #pragma unroll
    for (int u = 0; u < 4; ++u) {
        __half2 h0 = __floats2half2_rn(v[u].x, v[u].y);
        __half2 h1 = __floats2half2_rn(v[u].z, v[u].w);
        uint2 w;
        w.x = *reinterpret_cast<uint32_t*>(&h0);
        w.y = *reinterpret_cast<uint32_t*>(&h1);
        dst[blk_base + u * 256 + t] = w;
    }
}

__device__ __forceinline__ void mma_f16(float* d, uint32_t a0, uint32_t a1,
                                        uint32_t a2, uint32_t a3,
                                        uint32_t b0, uint32_t b1) {
    asm("mma.sync.aligned.m16n8k16.row.col.f32.f16.f16.f32 "
        "{%0,%1,%2,%3}, {%4,%5,%6,%7}, {%8,%9}, {%0,%1,%2,%3};"
        : "+f"(d[0]), "+f"(d[1]), "+f"(d[2]), "+f"(d[3])
        : "r"(a0), "r"(a1), "r"(a2), "r"(a3), "r"(b0), "r"(b1));
}

// N-dim permutation (dense q loads): GEMM col n = 16T+8h+2m+u holds
// physical i = phi(n) = 16m+4T+2h+u; rho = phi^{-1}.
__device__ __forceinline__ int rho_row(int i) {
    return (((i >> 2) & 3) << 4) | (((i >> 1) & 1) << 3) | (((i >> 4) & 3) << 1) | (i & 1);
}

__global__ void __launch_bounds__(NTHREADS, 2)
opn_mma_kernel(float* __restrict__ out)
{
    // smem (bytes): sA 36864 | sB 4 x 9216 | sOut 4096 -> 77824 B
    extern __shared__ __align__(16) __half dynsmem[];
    __half* sA   = dynsmem;
    __half* sB   = dynsmem + A_HALVES;
    float*  sOut = (float*)(sB + PCHUNK * B_HALVES);

    const int t    = threadIdx.x;
    const int ws   = t >> 5;    // warp strip: rows [ws*32, ws*32+32)
    const int lane = t & 31;
    const int m    = lane & 3;
    const int batch_base = blockIdx.x * BM;

    // ---- decode chunk id -> (r, first pair p0, #pairs np, first col c0) ----
    int cid = blockIdx.y, r = 0, pbase = 0;
    while (true) {
        int cnt = 31 - r;
        int nch = (cnt + PCHUNK - 1) >> 2;
        if (cid < nch) break;
        cid -= nch; pbase += cnt; ++r;
    }
    const int p0 = pbase + cid * PCHUNK;
    const int np = min(PCHUNK, (31 - r) - cid * PCHUNK);
    const int c0 = r + 1 + cid * PCHUNK;

    // ---- stage A: sA[b*ASTR + j] = emb_h[batch_base+b, r, j] ----
    {
        const __half* Pb = g_emb_h + (size_t)batch_base * EMB_ROW + r * EMBED;
        #pragma unroll
        for (int it = 0; it < 8; ++it) {
            int idx = it * NTHREADS + t;   // 0..2047 uint4 slots
            int b   = idx >> 3;            // 0..255
            int j8  = idx & 7;
            *(uint4*)(sA + b * ASTR + j8 * 8) =
                *(const uint4*)(Pb + (size_t)b * EMB_ROW + j8 * 8);
        }
    }
    // ---- stage all pairs' B tiles (one shot) ----
    {
        #pragma unroll
        for (int it = 0; it < 8; ++it) {
            int idx  = it * NTHREADS + t;  // 0..2047
            int pair = idx >> 9;           // 0..3
            int slot = idx & 511;
            if (pair < np) {
                int i  = slot >> 3;        // physical K row 0..63
                int j8 = slot & 7;
                *(uint4*)(sB + pair * B_HALVES + rho_row(i) * BSTR + j8 * 8) =
                    *(const uint4*)(g_ker_h + (size_t)(p0 + pair) * EMBED
                                    + (size_t)i * KER_ROW + j8 * 8);
            }
        }
    }
    __syncthreads();   // the ONLY barrier before the output sweep

    // ---- hoist A fragments into registers (shared across all pairs) ----
    const __half* Ap = sA + (ws * 32 + (lane >> 2)) * ASTR + 2 * m;
    uint32_t a[4][2][4];
    #pragma unroll
    for (int kt = 0; kt < 4; ++kt)
        #pragma unroll
        for (int mm = 0; mm < 2; ++mm) {
            const __half* Am = Ap + mm * 16 * ASTR + kt * 16;
            a[kt][mm][0] = *(const uint32_t*)(Am);
            a[kt][mm][1] = *(const uint32_t*)(Am + 8 * ASTR);
            a[kt][mm][2] = *(const uint32_t*)(Am + 8);
            a[kt][mm][3] = *(const uint32_t*)(Am + 8 * ASTR + 8);
        }

    const int bOff = (lane >> 2) * BSTR + 2 * m;

    // ---- barrier-free pair loop: all warps sweep pairs 0..np-1 ----
    #pragma unroll 1
    for (int j = 0; j < np; ++j) {
        const __half* Bp = sB + j * B_HALVES + bOff;

        float acc[2][8][4];
        #pragma unroll
        for (int mm = 0; mm < 2; ++mm)
            #pragma unroll
            for (int nt = 0; nt < 8; ++nt)
                #pragma unroll
                for (int u = 0; u < 4; ++u)
                    acc[mm][nt][u] = 0.f;

        #pragma unroll
        for (int kt = 0; kt < 4; ++kt) {
            #pragma unroll
            for (int nt = 0; nt < 8; ++nt) {
                const __half* Bn = Bp + nt * 8 * BSTR + kt * 16;
                uint32_t b0 = *(const uint32_t*)(Bn);
                uint32_t b1 = *(const uint32_t*)(Bn + 8);
                mma_f16(acc[0][nt], a[kt][0][0], a[kt][0][1], a[kt][0][2], a[kt][0][3], b0, b1);
                mma_f16(acc[1][nt], a[kt][1][0], a[kt][1][1], a[kt][1][2], a[kt][1][3], b0, b1);
            }
        }

        // ---- epilogue: dense q loads (lane m covers phys cols [16m,16m+16)) ----
        const int c = c0 + j;
        #pragma unroll
        for (int mm = 0; mm < 2; ++mm) {
            const int row0 = ws * 32 + mm * 16 + (lane >> 2);
            const __half* q0 = g_emb_h + (size_t)(batch_base + row0) * EMB_ROW
                             + c * EMBED + m * 16;
            const __half* q1 = q0 + 8 * EMB_ROW;

            uint4 lo0 = *(const uint4*)(q0);
            uint4 hi0 = *(const uint4*)(q0 + 8);
            uint4 lo1 = *(const uint4*)(q1);
            uint4 hi1 = *(const uint4*)(q1 + 8);

            float s0 = 0.f, s1 = 0.f;
            const uint32_t* w0[2] = { &lo0.x, &hi0.x };
            const uint32_t* w1[2] = { &lo1.x, &hi1.x };
            #pragma unroll
            for (int inst = 0; inst < 2; ++inst)
                #pragma unroll
                for (int p = 0; p < 4; ++p) {
                    float2 f0 = __half22float2(*reinterpret_cast<const __half2*>(&w0[inst][p]));
                    float2 f1 = __half22float2(*reinterpret_cast<const __half2*>(&w1[inst][p]));
                    const int nt = inst * 4 + p;
                    s0 += f0.x * acc[mm][nt][0] + f0.y * acc[mm][nt][1];
                    s1 += f1.x * acc[mm][nt][2] + f1.y * acc[mm][nt][3];
                }
            s0 += __shfl_xor_sync(0xffffffffu, s0, 1);
            s0 += __shfl_xor_sync(0xffffffffu, s0, 2);
            s1 += __shfl_xor_sync(0xffffffffu, s1, 1);
            s1 += __shfl_xor_sync(0xffffffffu, s1, 2);

            if (m == 0) {
                sOut[row0 * PCHUNK + j]       = s0;
                sOut[(row0 + 8) * PCHUNK + j] = s1;
            }
        }
    }
    __syncthreads();

    // ---- coalesced output sweep ----
    #pragma unroll
    for (int u = 0; u < 4; ++u) {
        int idx = t * 4 + u;               // 0..1023
        int b = idx >> 2;                  // 0..255
        int jj = idx & 3;
        if (jj < np)
            out[(size_t)(batch_base + b) * NPAIRS + p0 + jj] = sOut[idx];
    }
}

#define SMEM_TOTAL (A_HALVES * 2 + PCHUNK * B_HALVES * 2 + BM * PCHUNK * 4)  // 77824 B

extern "C" void kernel_launch(void* const* d_in, const int* in_sizes, int n_in,
                              void* d_out, int out_size) {
    const float* emb = (const float*)d_in[0];   // (2048, 32, 64) f32
    const float* ker = (const float*)d_in[1];   // (64, 496, 64) f32
    float* out = (float*)d_out;                 // (2048, 1, 496) f32
    (void)in_sizes; (void)n_in; (void)out_size;

    static bool attr_set = false;
    if (!attr_set) {
        cudaFuncSetAttribute(opn_mma_kernel,
                             cudaFuncAttributeMaxDynamicSharedMemorySize, SMEM_TOTAL);
        attr_set = true;
    }
    conv_kernel<<<EMB_CONV_BLOCKS + KER_CONV_BLOCKS, 256>>>(emb, ker);
    dim3 grid(BATCH / BM, NCHUNKS);
    opn_mma_kernel<<<grid, NTHREADS, SMEM_TOTAL>>>(out);
}